// round 12
// baseline (speedup 1.0000x reference)
#include <cuda_runtime.h>
#include <math.h>

#define NB 32
#define NS 48000
#define L_CHUNK 32
#define NCH (NS / L_CHUNK)      /* 1500 */
#define NQUAD (NCH / 4)         /* 375 */
#define PD 8                    /* out prefetch depth */
#define PD1 4                   /* map prefetch depth */
#define PLANE (NS * NB)

// 3 planes of float4, layout [n][b]:
//   plane0 = (sA_low, invL, sA_high, invH)
//   plane1 = (cw_mid, alA, alrA, invM)
//   plane2 = (sv, alpha_a*y_attack, 1-alpha_a, 0)
__device__ float4 g_p0[(size_t)PLANE];
__device__ float4 g_p1[(size_t)PLANE];
__device__ float4 g_p2[(size_t)PLANE];
// Per (chunk, lane) affine map: 30 floats, [c][b][30]
__device__ float g_maps[(size_t)NCH * NB * 30];
// Inclusive chunk-end states: 6 planes of [c][b]
__device__ float g_state[6 * (size_t)NCH * NB];

// shelf constants
#define CW_L  0.9994645875f     /* cos(2pi*250/48000) */
#define ALC_L 0.0231360485f     /* sin(w0_l)*sqrt(2)/2 */
#define CW_H  0.8660254038f     /* cos(pi/6) */
#define ALC_H 0.3535533906f     /* sin(pi/6)*sqrt(2)/2 */
#define KDB   0.0830482024f     /* log2(10)/40 */

// ---------------- fast approx helpers ----------------
__device__ __forceinline__ float f_tanh(float x) {
    float r; asm("tanh.approx.f32 %0, %1;" : "=f"(r) : "f"(x)); return r;
}
__device__ __forceinline__ float f_rcp(float x) {
    float r; asm("rcp.approx.f32 %0, %1;" : "=f"(r) : "f"(x)); return r;
}
__device__ __forceinline__ float f_ex2(float x) {
    float r; asm("ex2.approx.f32 %0, %1;" : "=f"(r) : "f"(x)); return r;
}

// ---------------------------------------------------------------------------
// Coefficient reconstruction: pure FMA/MUL (reciprocals precomputed).
// ---------------------------------------------------------------------------
__device__ __forceinline__ void make_coefs(const float4& pa, const float4& pb, float c[15])
{
    {   // low shelf: pa.x = sA, pa.y = 1/a0
        float sA = pa.x, inv = pa.y;
        float A  = sA * sA;
        float t  = 2.0f * sA * ALC_L;
        float ap = A + 1.0f, am = A - 1.0f;
        c[0] = A * (ap - am * CW_L + t) * inv;
        c[1] = 2.0f * A * (am - ap * CW_L) * inv;
        c[2] = A * (ap - am * CW_L - t) * inv;
        c[3] = -2.0f * (am + ap * CW_L) * inv;
        c[4] = (ap + am * CW_L - t) * inv;
    }
    {   // mid peaking: pb = (cw, alA, alrA, 1/a0)
        float cw = pb.x, alA = pb.y, alrA = pb.z, inv = pb.w;
        c[5] = (1.0f + alA) * inv;
        c[6] = -2.0f * cw * inv;
        c[7] = (1.0f - alA) * inv;
        c[8] = c[6];
        c[9] = (1.0f - alrA) * inv;
    }
    {   // high shelf: pa.z = sA, pa.w = 1/a0
        float sA = pa.z, inv = pa.w;
        float A  = sA * sA;
        float t  = 2.0f * sA * ALC_H;
        float ap = A + 1.0f, am = A - 1.0f;
        c[10] = A * (ap + am * CW_H + t) * inv;
        c[11] = -2.0f * A * (am + ap * CW_H) * inv;
        c[12] = A * (ap + am * CW_H - t) * inv;
        c[13] = 2.0f * (am - ap * CW_H) * inv;
        c[14] = (ap - am * CW_H - t) * inv;
    }
}

// ---------------------------------------------------------------------------
// Kernel 1: transient sep, waveshaper, derived-param precompute.
// Block (16, 32): tx = sample-in-tile, ty = batch row.
// ---------------------------------------------------------------------------
__global__ void __launch_bounds__(512) prep_kernel(
        const float* __restrict__ x,
        const float* __restrict__ alpha,
        const float* __restrict__ beta,
        const float* __restrict__ low_db,
        const float* __restrict__ mid_db,
        const float* __restrict__ mid_fc,
        const float* __restrict__ mid_Q,
        const float* __restrict__ high_db,
        const float* __restrict__ alpha_a)
{
    __shared__ float4 st4[3 * 16 * 33];

    const int tx = threadIdx.x;
    const int ty = threadIdx.y;
    const int nbase = blockIdx.x * 16;
    const int n = nbase + tx;
    const int b = ty;
    const int i = b * NS + n;

    const float* xr = x + (size_t)b * NS;
    float xv = xr[n];
    float env = 0.0f;
    #pragma unroll
    for (int d = -7; d <= 7; ++d) {
        int j = n + d;
        if (j >= 0 && j < NS) env += fabsf(xr[j]);
    }
    env *= (1.0f / 15.0f);
    float xa = fabsf(xv);
    float gate = fmaf(0.5f, f_tanh(4.0f * (xa - env)), 0.5f);
    float av = gate * xv;
    float sv = (1.0f - gate) * xv;

    float be_ = beta[i];
    float ya = f_tanh(fmaf(alpha[i], av, be_)) - f_tanh(be_);

    float sA_l = f_ex2(low_db[i] * (0.5f * KDB));
    float sA_h = f_ex2(high_db[i] * (0.5f * KDB));

    float invL, invH;
    {
        float A = sA_l * sA_l, t = 2.0f * sA_l * ALC_L;
        invL = f_rcp((A + 1.0f) + (A - 1.0f) * CW_L + t);
    }
    {
        float A = sA_h * sA_h, t = 2.0f * sA_h * ALC_H;
        invH = f_rcp((A + 1.0f) - (A - 1.0f) * CW_H + t);
    }

    float A_m = f_ex2(mid_db[i] * KDB);
    float w0  = mid_fc[i] * 1.30899693e-4f;   // 2*pi/48000
    float sw = __sinf(w0), cw = __cosf(w0);
    float alq  = sw * 0.5f * f_rcp(mid_Q[i]);
    float alA  = alq * A_m;
    float alrA = alq * f_rcp(A_m);
    float invM = f_rcp(1.0f + alrA);

    float aav = alpha_a[i];

    st4[0 * (16 * 33) + tx * 33 + b] = make_float4(sA_l, invL, sA_h, invH);
    st4[1 * (16 * 33) + tx * 33 + b] = make_float4(cw, alA, alrA, invM);
    st4[2 * (16 * 33) + tx * 33 + b] = make_float4(sv, aav * ya, 1.0f - aav, 0.0f);

    __syncthreads();
    {
        const int tid = ty * 16 + tx;
        const int cb  = tid & 31;
        const int ctx = tid >> 5;
        const size_t o = (size_t)(nbase + ctx) * NB + cb;
        g_p0[o] = st4[0 * (16 * 33) + ctx * 33 + cb];
        g_p1[o] = st4[1 * (16 * 33) + ctx * 33 + cb];
        g_p2[o] = st4[2 * (16 * 33) + ctx * 33 + cb];
    }
}

// ---------------------------------------------------------------------------
// Step primitives on coefficient array c[15].
// ---------------------------------------------------------------------------
__device__ __forceinline__ float stepF(const float c[15], float u[6], float v)
{
    float y1 = fmaf(c[0], v, u[0]);
    float a  = fmaf(c[1], v, fmaf(-c[3], y1, u[1]));
    float bb = fmaf(c[2], v, -c[4] * y1);
    float y2 = fmaf(c[5], y1, u[2]);
    float cc = fmaf(c[6], y1, fmaf(-c[8], y2, u[3]));
    float dd = fmaf(c[7], y1, -c[9] * y2);
    float y3 = fmaf(c[10], y2, u[4]);
    float ee = fmaf(c[11], y2, fmaf(-c[13], y3, u[5]));
    float ff = fmaf(c[12], y2, -c[14] * y3);
    u[0]=a; u[1]=bb; u[2]=cc; u[3]=dd; u[4]=ee; u[5]=ff;
    return y3;
}
__device__ __forceinline__ void stepM(const float c[15], float w[4])
{
    float y2 = w[0];
    float a  = fmaf(-c[8], y2, w[1]);
    float bb = -c[9] * y2;
    float y3 = fmaf(c[10], y2, w[2]);
    float cc = fmaf(c[11], y2, fmaf(-c[13], y3, w[3]));
    float dd = fmaf(c[12], y2, -c[14] * y3);
    w[0]=a; w[1]=bb; w[2]=cc; w[3]=dd;
}
__device__ __forceinline__ void stepH(const float c[15], float w[2])
{
    float y3 = w[0];
    float a  = fmaf(-c[13], y3, w[1]);
    float bb = -c[14] * y3;
    w[0]=a; w[1]=bb;
}

// ---------------------------------------------------------------------------
// Pass 1: per-chunk affine map, one warp per 32-sample chunk.
// Map record (30 floats): c1[6] c2[6] c3[4] c4[4] c5[2] c6[2] d[6]
// ---------------------------------------------------------------------------
__global__ void __launch_bounds__(32) map_kernel()
{
    const int c = blockIdx.x;
    const int lane = threadIdx.x;
    const int n0 = c * L_CHUNK;

    const float4* __restrict__ p0 = g_p0;
    const float4* __restrict__ p1 = g_p1;
    const float4* __restrict__ p2 = g_p2;

    float u1[6] = {1,0,0,0,0,0};
    float u2[6] = {0,1,0,0,0,0};
    float u3[4] = {1,0,0,0};
    float u4[4] = {0,1,0,0};
    float u5[2] = {1,0};
    float u6[2] = {0,1};
    float dd[6] = {0,0,0,0,0,0};

    float4 qa[PD1], qb[PD1], qc[PD1];
    #pragma unroll
    for (int d = 0; d < PD1; ++d) {
        int ofs = (n0 + d) * NB + lane;
        qa[d] = p0[ofs]; qb[d] = p1[ofs]; qc[d] = p2[ofs];
    }

    #pragma unroll
    for (int j = 0; j < 32; ++j) {
        const int slot = j & (PD1 - 1);
        float4 a = qa[slot], b = qb[slot], cc2 = qc[slot];
        int nf = n0 + j + PD1;
        if (nf > NS - 1) nf = NS - 1;
        int ofs = nf * NB + lane;
        qa[slot] = p0[ofs]; qb[slot] = p1[ofs]; qc[slot] = p2[ofs];

        float cf[15];
        make_coefs(a, b, cf);

        stepF(cf, u1, 0.0f);
        stepF(cf, u2, 0.0f);
        stepM(cf, u3);
        stepM(cf, u4);
        stepH(cf, u5);
        stepH(cf, u6);
        stepF(cf, dd, cc2.x);   // v = sv
    }

    float* rec = g_maps + (size_t)(c * NB + lane) * 30;
    #pragma unroll
    for (int k = 0; k < 6; ++k) rec[k]      = u1[k];
    #pragma unroll
    for (int k = 0; k < 6; ++k) rec[6 + k]  = u2[k];
    #pragma unroll
    for (int k = 0; k < 4; ++k) rec[12 + k] = u3[k];
    #pragma unroll
    for (int k = 0; k < 4; ++k) rec[16 + k] = u4[k];
    rec[20] = u5[0]; rec[21] = u5[1];
    rec[22] = u6[0]; rec[23] = u6[1];
    #pragma unroll
    for (int k = 0; k < 6; ++k) rec[24 + k] = dd[k];
}

// ---------------------------------------------------------------------------
// Map compose helpers (block-lower-triangular sparsity).
// ---------------------------------------------------------------------------
__device__ __forceinline__ void bmv_full(const float* B, const float* w, float* r)
{
    r[0] = w[0]*B[0] + w[1]*B[6];
    r[1] = w[0]*B[1] + w[1]*B[7];
    r[2] = w[0]*B[2] + w[1]*B[8]  + w[2]*B[12] + w[3]*B[16];
    r[3] = w[0]*B[3] + w[1]*B[9]  + w[2]*B[13] + w[3]*B[17];
    r[4] = w[0]*B[4] + w[1]*B[10] + w[2]*B[14] + w[3]*B[18] + w[4]*B[20] + w[5]*B[22];
    r[5] = w[0]*B[5] + w[1]*B[11] + w[2]*B[15] + w[3]*B[19] + w[4]*B[21] + w[5]*B[23];
}
__device__ __forceinline__ void bmv_mid(const float* B, const float* w, float* r)
{
    r[0] = w[0]*B[12] + w[1]*B[16];
    r[1] = w[0]*B[13] + w[1]*B[17];
    r[2] = w[0]*B[14] + w[1]*B[18] + w[2]*B[20] + w[3]*B[22];
    r[3] = w[0]*B[15] + w[1]*B[19] + w[2]*B[21] + w[3]*B[23];
}
__device__ __forceinline__ void bmv_high(const float* B, const float* w, float* r)
{
    r[0] = w[0]*B[20] + w[1]*B[22];
    r[1] = w[0]*B[21] + w[1]*B[23];
}
// C = B after A  (A applied first)
__device__ __forceinline__ void compose(const float* A, const float* B, float* C)
{
    bmv_full(B, A + 0,  C + 0);
    bmv_full(B, A + 6,  C + 6);
    bmv_mid (B, A + 12, C + 12);
    bmv_mid (B, A + 16, C + 16);
    bmv_high(B, A + 20, C + 20);
    bmv_high(B, A + 22, C + 22);
    float t6[6];
    bmv_full(B, A + 24, t6);
    #pragma unroll
    for (int k = 0; k < 6; ++k) C[24 + k] = t6[k] + B[24 + k];
}

// apply map A to state w: w <- M(A)w + d(A)
__device__ __forceinline__ void apply_map(const float* A, float w[6])
{
    float r[6];
    bmv_full(A, w, r);
    #pragma unroll
    for (int k = 0; k < 6; ++k) w[k] = r[k] + A[24 + k];
}

// ---------------------------------------------------------------------------
// Scan: one block per batch lane. Each thread quad-composes maps
// (4t..4t+3) in registers, Hillis-Steele over 375 quads in smem, then
// emits all 4 inclusive chunk-end states (leading 3 by progressive apply).
// ---------------------------------------------------------------------------
__global__ void __launch_bounds__(384) scan_kernel()
{
    __shared__ float sm[NQUAD * 30];    // 45000 B
    const int t = threadIdx.x;
    const int b = blockIdx.x;
    const bool on = (t < NQUAD);

    if (on) {
        float A0[30], A1[30], P01[30], P23[30], P[30];
        const float* s0 = g_maps + (size_t)((4 * t)     * NB + b) * 30;
        const float* s1 = g_maps + (size_t)((4 * t + 1) * NB + b) * 30;
        #pragma unroll
        for (int k = 0; k < 30; ++k) A0[k] = s0[k];
        #pragma unroll
        for (int k = 0; k < 30; ++k) A1[k] = s1[k];
        compose(A0, A1, P01);
        const float* s2 = g_maps + (size_t)((4 * t + 2) * NB + b) * 30;
        const float* s3 = g_maps + (size_t)((4 * t + 3) * NB + b) * 30;
        #pragma unroll
        for (int k = 0; k < 30; ++k) A0[k] = s2[k];
        #pragma unroll
        for (int k = 0; k < 30; ++k) A1[k] = s3[k];
        compose(A0, A1, P23);
        compose(P01, P23, P);
        #pragma unroll
        for (int k = 0; k < 30; ++k) sm[t * 30 + k] = P[k];
    }
    __syncthreads();

    for (int off = 1; off < NQUAD; off <<= 1) {
        float Ap[30], Bp[30];
        const bool act = on && (t >= off);
        if (act) {
            #pragma unroll
            for (int k = 0; k < 30; ++k) Ap[k] = sm[(t - off) * 30 + k];
            #pragma unroll
            for (int k = 0; k < 30; ++k) Bp[k] = sm[t * 30 + k];
        }
        __syncthreads();
        if (act) {
            float C[30];
            compose(Ap, Bp, C);
            #pragma unroll
            for (int k = 0; k < 30; ++k) sm[t * 30 + k] = C[k];
        }
        __syncthreads();
    }

    if (on) {
        // state after all chunks through 4t+3 = inclusive quad scan's d
        #pragma unroll
        for (int k = 0; k < 6; ++k)
            g_state[(size_t)k * (NCH * NB) + (4 * t + 3) * NB + b] = sm[t * 30 + 24 + k];

        // progressive states for chunks 4t, 4t+1, 4t+2
        float w[6];
        if (t == 0) {
            #pragma unroll
            for (int k = 0; k < 6; ++k) w[k] = 0.0f;
        } else {
            #pragma unroll
            for (int k = 0; k < 6; ++k) w[k] = sm[(t - 1) * 30 + 24 + k];
        }
        float A[30];
        #pragma unroll
        for (int q = 0; q < 3; ++q) {
            const float* src = g_maps + (size_t)((4 * t + q) * NB + b) * 30;
            #pragma unroll
            for (int k = 0; k < 30; ++k) A[k] = src[k];
            apply_map(A, w);
            #pragma unroll
            for (int k = 0; k < 6; ++k)
                g_state[(size_t)k * (NCH * NB) + (4 * t + q) * NB + b] = w[k];
        }
    }
}

// ---------------------------------------------------------------------------
// Pass 2: final IIR per 32-sample chunk with exact initial state.
// ---------------------------------------------------------------------------
__global__ void __launch_bounds__(32) out_kernel(float* __restrict__ out)
{
    const int c = blockIdx.x;
    const int lane = threadIdx.x;
    const int n0 = c * L_CHUNK;

    const float4* __restrict__ p0 = g_p0;
    const float4* __restrict__ p1 = g_p1;
    const float4* __restrict__ p2 = g_p2;

    float s[6] = {0,0,0,0,0,0};
    if (c > 0) {
        #pragma unroll
        for (int k = 0; k < 6; ++k)
            s[k] = g_state[(size_t)k * (NCH * NB) + (c - 1) * NB + lane];
    }

    float4 qa[PD], qb[PD], qc[PD];
    #pragma unroll
    for (int d = 0; d < PD; ++d) {
        int ofs = (n0 + d) * NB + lane;
        qa[d] = p0[ofs]; qb[d] = p1[ofs]; qc[d] = p2[ofs];
    }

    __shared__ float buf[32 * 33];

    #pragma unroll
    for (int j = 0; j < 32; ++j) {
        const int slot = j & (PD - 1);
        float4 a = qa[slot], b = qb[slot], m = qc[slot];
        int nf = n0 + j + PD;
        if (nf > NS - 1) nf = NS - 1;
        int ofs = nf * NB + lane;
        qa[slot] = p0[ofs]; qb[slot] = p1[ofs]; qc[slot] = p2[ofs];

        float cf[15];
        make_coefs(a, b, cf);
        float ys = stepF(cf, s, m.x);
        buf[lane * 33 + j] = fmaf(m.z, ys, m.y);
    }
    __syncwarp();
    const int nw = n0 + lane;
    #pragma unroll
    for (int b2 = 0; b2 < 32; ++b2)
        out[b2 * NS + nw] = buf[b2 * 33 + lane];
}

extern "C" void kernel_launch(void* const* d_in, const int* in_sizes, int n_in,
                              void* d_out, int out_size)
{
    const float* x       = (const float*)d_in[0];
    const float* alpha   = (const float*)d_in[1];
    const float* beta    = (const float*)d_in[2];
    const float* low_db  = (const float*)d_in[3];
    const float* mid_db  = (const float*)d_in[4];
    const float* mid_fc  = (const float*)d_in[5];
    const float* mid_Q   = (const float*)d_in[6];
    const float* high_db = (const float*)d_in[7];
    const float* alpha_a = (const float*)d_in[8];
    float* out = (float*)d_out;

    dim3 pb(16, 32);
    prep_kernel<<<NS / 16, pb>>>(x, alpha, beta, low_db, mid_db, mid_fc,
                                 mid_Q, high_db, alpha_a);
    map_kernel<<<NCH, 32>>>();
    scan_kernel<<<NB, 384>>>();
    out_kernel<<<NCH, 32>>>(out);
}

// round 15
// speedup vs baseline: 1.3268x; 1.3268x over previous
#include <cuda_runtime.h>
#include <math.h>

#define NB 32
#define NS 48000
#define L_CHUNK 64
#define NCH (NS / L_CHUNK)      /* 750 */
#define NPAIR (NCH / 2)         /* 375 */
#define PD1 4                   /* map prefetch depth */
#define PLANE (NS * NB)

// 3 planes of float4, layout [n][b]:
//   plane0 = (sA_low, invL, sA_high, invH)
//   plane1 = (cw_mid, alA, alrA, invM)
//   plane2 = (sv, alpha_a*y_attack, 1-alpha_a, 0)
__device__ float4 g_p0[(size_t)PLANE];
__device__ float4 g_p1[(size_t)PLANE];
__device__ float4 g_p2[(size_t)PLANE];
// Per-sample mix-folded output row: y = ga.s0123 + gb.s45 + gb.z
__device__ float4 g_ga[(size_t)PLANE];
__device__ float4 g_gb[(size_t)PLANE];
// Per (chunk, lane) affine map: 30 floats, [c][b][30]
__device__ float g_maps[(size_t)NCH * NB * 30];
// Inclusive chunk-end states: 6 planes of [c][b]
__device__ float g_state[6 * (size_t)NCH * NB];

// shelf constants
#define CW_L  0.9994645875f     /* cos(2pi*250/48000) */
#define ALC_L 0.0231360485f     /* sin(w0_l)*sqrt(2)/2 */
#define CW_H  0.8660254038f     /* cos(pi/6) */
#define ALC_H 0.3535533906f     /* sin(pi/6)*sqrt(2)/2 */
#define KDB   0.0830482024f     /* log2(10)/40 */

// ---------------- fast approx helpers ----------------
__device__ __forceinline__ float f_tanh(float x) {
    float r; asm("tanh.approx.f32 %0, %1;" : "=f"(r) : "f"(x)); return r;
}
__device__ __forceinline__ float f_rcp(float x) {
    float r; asm("rcp.approx.f32 %0, %1;" : "=f"(r) : "f"(x)); return r;
}
__device__ __forceinline__ float f_ex2(float x) {
    float r; asm("ex2.approx.f32 %0, %1;" : "=f"(r) : "f"(x)); return r;
}

// ---------------------------------------------------------------------------
// Coefficient reconstruction: pure FMA/MUL (reciprocals precomputed).
// ---------------------------------------------------------------------------
__device__ __forceinline__ void make_coefs(const float4& pa, const float4& pb, float c[15])
{
    {   // low shelf: pa.x = sA, pa.y = 1/a0
        float sA = pa.x, inv = pa.y;
        float A  = sA * sA;
        float t  = 2.0f * sA * ALC_L;
        float ap = A + 1.0f, am = A - 1.0f;
        c[0] = A * (ap - am * CW_L + t) * inv;
        c[1] = 2.0f * A * (am - ap * CW_L) * inv;
        c[2] = A * (ap - am * CW_L - t) * inv;
        c[3] = -2.0f * (am + ap * CW_L) * inv;
        c[4] = (ap + am * CW_L - t) * inv;
    }
    {   // mid peaking: pb = (cw, alA, alrA, 1/a0)
        float cw = pb.x, alA = pb.y, alrA = pb.z, inv = pb.w;
        c[5] = (1.0f + alA) * inv;
        c[6] = -2.0f * cw * inv;
        c[7] = (1.0f - alA) * inv;
        c[8] = c[6];
        c[9] = (1.0f - alrA) * inv;
    }
    {   // high shelf: pa.z = sA, pa.w = 1/a0
        float sA = pa.z, inv = pa.w;
        float A  = sA * sA;
        float t  = 2.0f * sA * ALC_H;
        float ap = A + 1.0f, am = A - 1.0f;
        c[10] = A * (ap + am * CW_H + t) * inv;
        c[11] = -2.0f * A * (am + ap * CW_H) * inv;
        c[12] = A * (ap + am * CW_H - t) * inv;
        c[13] = 2.0f * (am - ap * CW_H) * inv;
        c[14] = (ap - am * CW_H - t) * inv;
    }
}

// ---------------------------------------------------------------------------
// Kernel 1: transient sep, waveshaper, derived-param precompute.
// ---------------------------------------------------------------------------
__global__ void __launch_bounds__(512) prep_kernel(
        const float* __restrict__ x,
        const float* __restrict__ alpha,
        const float* __restrict__ beta,
        const float* __restrict__ low_db,
        const float* __restrict__ mid_db,
        const float* __restrict__ mid_fc,
        const float* __restrict__ mid_Q,
        const float* __restrict__ high_db,
        const float* __restrict__ alpha_a)
{
    __shared__ float4 st4[3 * 16 * 33];

    const int tx = threadIdx.x;
    const int ty = threadIdx.y;
    const int nbase = blockIdx.x * 16;
    const int n = nbase + tx;
    const int b = ty;
    const int i = b * NS + n;

    const float* xr = x + (size_t)b * NS;
    float xv = xr[n];
    float env = 0.0f;
    #pragma unroll
    for (int d = -7; d <= 7; ++d) {
        int j = n + d;
        if (j >= 0 && j < NS) env += fabsf(xr[j]);
    }
    env *= (1.0f / 15.0f);
    float xa = fabsf(xv);
    float gate = fmaf(0.5f, f_tanh(4.0f * (xa - env)), 0.5f);
    float av = gate * xv;
    float sv = (1.0f - gate) * xv;

    float be_ = beta[i];
    float ya = f_tanh(fmaf(alpha[i], av, be_)) - f_tanh(be_);

    float sA_l = f_ex2(low_db[i] * (0.5f * KDB));
    float sA_h = f_ex2(high_db[i] * (0.5f * KDB));

    float invL, invH;
    {
        float A = sA_l * sA_l, t = 2.0f * sA_l * ALC_L;
        invL = f_rcp((A + 1.0f) + (A - 1.0f) * CW_L + t);
    }
    {
        float A = sA_h * sA_h, t = 2.0f * sA_h * ALC_H;
        invH = f_rcp((A + 1.0f) - (A - 1.0f) * CW_H + t);
    }

    float A_m = f_ex2(mid_db[i] * KDB);
    float w0  = mid_fc[i] * 1.30899693e-4f;   // 2*pi/48000
    float sw = __sinf(w0), cw = __cosf(w0);
    float alq  = sw * 0.5f * f_rcp(mid_Q[i]);
    float alA  = alq * A_m;
    float alrA = alq * f_rcp(A_m);
    float invM = f_rcp(1.0f + alrA);

    float aav = alpha_a[i];

    st4[0 * (16 * 33) + tx * 33 + b] = make_float4(sA_l, invL, sA_h, invH);
    st4[1 * (16 * 33) + tx * 33 + b] = make_float4(cw, alA, alrA, invM);
    st4[2 * (16 * 33) + tx * 33 + b] = make_float4(sv, aav * ya, 1.0f - aav, 0.0f);

    __syncthreads();
    {
        const int tid = ty * 16 + tx;
        const int cb  = tid & 31;
        const int ctx = tid >> 5;
        const size_t o = (size_t)(nbase + ctx) * NB + cb;
        g_p0[o] = st4[0 * (16 * 33) + ctx * 33 + cb];
        g_p1[o] = st4[1 * (16 * 33) + ctx * 33 + cb];
        g_p2[o] = st4[2 * (16 * 33) + ctx * 33 + cb];
    }
}

// ---------------------------------------------------------------------------
// Step primitives on coefficient array c[15]. Each returns the tone-stack
// OUTPUT (y3) produced by this step — the output-row component.
// ---------------------------------------------------------------------------
__device__ __forceinline__ float stepF(const float c[15], float u[6], float v)
{
    float y1 = fmaf(c[0], v, u[0]);
    float a  = fmaf(c[1], v, fmaf(-c[3], y1, u[1]));
    float bb = fmaf(c[2], v, -c[4] * y1);
    float y2 = fmaf(c[5], y1, u[2]);
    float cc = fmaf(c[6], y1, fmaf(-c[8], y2, u[3]));
    float dd = fmaf(c[7], y1, -c[9] * y2);
    float y3 = fmaf(c[10], y2, u[4]);
    float ee = fmaf(c[11], y2, fmaf(-c[13], y3, u[5]));
    float ff = fmaf(c[12], y2, -c[14] * y3);
    u[0]=a; u[1]=bb; u[2]=cc; u[3]=dd; u[4]=ee; u[5]=ff;
    return y3;
}
__device__ __forceinline__ float stepM(const float c[15], float w[4])
{
    float y2 = w[0];
    float a  = fmaf(-c[8], y2, w[1]);
    float bb = -c[9] * y2;
    float y3 = fmaf(c[10], y2, w[2]);
    float cc = fmaf(c[11], y2, fmaf(-c[13], y3, w[3]));
    float dd = fmaf(c[12], y2, -c[14] * y3);
    w[0]=a; w[1]=bb; w[2]=cc; w[3]=dd;
    return y3;
}
__device__ __forceinline__ float stepH(const float c[15], float w[2])
{
    float y3 = w[0];
    float a  = fmaf(-c[13], y3, w[1]);
    float bb = -c[14] * y3;
    w[0]=a; w[1]=bb;
    return y3;
}

// ---------------------------------------------------------------------------
// Pass 1: per-chunk affine map + per-sample mix-folded OUTPUT ROW.
// One warp per 64-sample chunk. The 7 column pushes' y3 returns are exactly
// (G_n[0..5], H_n): y_n = G_n . s0 + H_n. Stored folded with the mix:
//   ga = m.z*(G0..G3),  gb = (m.z*G4, m.z*G5, m.z*H + m.y, 0)
// ---------------------------------------------------------------------------
__global__ void __launch_bounds__(32) map_kernel()
{
    const int c = blockIdx.x;
    const int lane = threadIdx.x;
    const int n0 = c * L_CHUNK;

    const float4* __restrict__ p0 = g_p0;
    const float4* __restrict__ p1 = g_p1;
    const float4* __restrict__ p2 = g_p2;

    float u1[6] = {1,0,0,0,0,0};
    float u2[6] = {0,1,0,0,0,0};
    float u3[4] = {1,0,0,0};
    float u4[4] = {0,1,0,0};
    float u5[2] = {1,0};
    float u6[2] = {0,1};
    float dd[6] = {0,0,0,0,0,0};

    float4 qa[PD1], qb[PD1], qc[PD1];
    #pragma unroll
    for (int d = 0; d < PD1; ++d) {
        int ofs = (n0 + d) * NB + lane;
        qa[d] = p0[ofs]; qb[d] = p1[ofs]; qc[d] = p2[ofs];
    }

    for (int t = 0; t < L_CHUNK / 32; ++t) {
        const int nb_ = n0 + (t << 5);
        #pragma unroll
        for (int j = 0; j < 32; ++j) {
            const int slot = j & (PD1 - 1);
            float4 a = qa[slot], b = qb[slot], cc2 = qc[slot];
            int nf = nb_ + j + PD1;
            if (nf > NS - 1) nf = NS - 1;
            int ofs = nf * NB + lane;
            qa[slot] = p0[ofs]; qb[slot] = p1[ofs]; qc[slot] = p2[ofs];

            float cf[15];
            make_coefs(a, b, cf);

            float g1 = stepF(cf, u1, 0.0f);
            float g2 = stepF(cf, u2, 0.0f);
            float g3 = stepM(cf, u3);
            float g4 = stepM(cf, u4);
            float g5 = stepH(cf, u5);
            float g6 = stepH(cf, u6);
            float hy = stepF(cf, dd, cc2.x);   // v = sv

            float z = cc2.z;                   // 1 - alpha_a
            int oc = (nb_ + j) * NB + lane;
            g_ga[oc] = make_float4(z * g1, z * g2, z * g3, z * g4);
            g_gb[oc] = make_float4(z * g5, z * g6, fmaf(z, hy, cc2.y), 0.0f);
        }
    }

    float* rec = g_maps + (size_t)(c * NB + lane) * 30;
    #pragma unroll
    for (int k = 0; k < 6; ++k) rec[k]      = u1[k];
    #pragma unroll
    for (int k = 0; k < 6; ++k) rec[6 + k]  = u2[k];
    #pragma unroll
    for (int k = 0; k < 4; ++k) rec[12 + k] = u3[k];
    #pragma unroll
    for (int k = 0; k < 4; ++k) rec[16 + k] = u4[k];
    rec[20] = u5[0]; rec[21] = u5[1];
    rec[22] = u6[0]; rec[23] = u6[1];
    #pragma unroll
    for (int k = 0; k < 6; ++k) rec[24 + k] = dd[k];
}

// ---------------------------------------------------------------------------
// Map compose helpers (block-lower-triangular sparsity).
// ---------------------------------------------------------------------------
__device__ __forceinline__ void bmv_full(const float* B, const float* w, float* r)
{
    r[0] = w[0]*B[0] + w[1]*B[6];
    r[1] = w[0]*B[1] + w[1]*B[7];
    r[2] = w[0]*B[2] + w[1]*B[8]  + w[2]*B[12] + w[3]*B[16];
    r[3] = w[0]*B[3] + w[1]*B[9]  + w[2]*B[13] + w[3]*B[17];
    r[4] = w[0]*B[4] + w[1]*B[10] + w[2]*B[14] + w[3]*B[18] + w[4]*B[20] + w[5]*B[22];
    r[5] = w[0]*B[5] + w[1]*B[11] + w[2]*B[15] + w[3]*B[19] + w[4]*B[21] + w[5]*B[23];
}
__device__ __forceinline__ void bmv_mid(const float* B, const float* w, float* r)
{
    r[0] = w[0]*B[12] + w[1]*B[16];
    r[1] = w[0]*B[13] + w[1]*B[17];
    r[2] = w[0]*B[14] + w[1]*B[18] + w[2]*B[20] + w[3]*B[22];
    r[3] = w[0]*B[15] + w[1]*B[19] + w[2]*B[21] + w[3]*B[23];
}
__device__ __forceinline__ void bmv_high(const float* B, const float* w, float* r)
{
    r[0] = w[0]*B[20] + w[1]*B[22];
    r[1] = w[0]*B[21] + w[1]*B[23];
}
// C = B after A  (A applied first)
__device__ __forceinline__ void compose(const float* A, const float* B, float* C)
{
    bmv_full(B, A + 0,  C + 0);
    bmv_full(B, A + 6,  C + 6);
    bmv_mid (B, A + 12, C + 12);
    bmv_mid (B, A + 16, C + 16);
    bmv_high(B, A + 20, C + 20);
    bmv_high(B, A + 22, C + 22);
    float t6[6];
    bmv_full(B, A + 24, t6);
    #pragma unroll
    for (int k = 0; k < 6; ++k) C[24 + k] = t6[k] + B[24 + k];
}

// ---------------------------------------------------------------------------
// Scan: one block per batch lane. Pair-compose in registers, Hillis-Steele
// over 375 pairs in smem, emit both chunk-end states.
// ---------------------------------------------------------------------------
__global__ void __launch_bounds__(384) scan_kernel()
{
    __shared__ float sm[NPAIR * 30];    // 45000 B
    const int t = threadIdx.x;
    const int b = blockIdx.x;
    const bool on = (t < NPAIR);

    float A[30];
    if (on) {
        const float* srcA = g_maps + (size_t)((2 * t)     * NB + b) * 30;
        const float* srcB = g_maps + (size_t)((2 * t + 1) * NB + b) * 30;
        float Bm[30], P[30];
        #pragma unroll
        for (int k = 0; k < 30; ++k) A[k]  = srcA[k];
        #pragma unroll
        for (int k = 0; k < 30; ++k) Bm[k] = srcB[k];
        compose(A, Bm, P);
        #pragma unroll
        for (int k = 0; k < 30; ++k) sm[t * 30 + k] = P[k];
    }
    __syncthreads();

    for (int off = 1; off < NPAIR; off <<= 1) {
        float Ap[30], Bp[30];
        const bool act = on && (t >= off);
        if (act) {
            #pragma unroll
            for (int k = 0; k < 30; ++k) Ap[k] = sm[(t - off) * 30 + k];
            #pragma unroll
            for (int k = 0; k < 30; ++k) Bp[k] = sm[t * 30 + k];
        }
        __syncthreads();
        if (act) {
            float C[30];
            compose(Ap, Bp, C);
            #pragma unroll
            for (int k = 0; k < 30; ++k) sm[t * 30 + k] = C[k];
        }
        __syncthreads();
    }

    if (on) {
        #pragma unroll
        for (int k = 0; k < 6; ++k)
            g_state[(size_t)k * (NCH * NB) + (2 * t + 1) * NB + b] = sm[t * 30 + 24 + k];
        float se[6];
        if (t == 0) {
            #pragma unroll
            for (int k = 0; k < 6; ++k) se[k] = A[24 + k];
        } else {
            float w[6];
            #pragma unroll
            for (int k = 0; k < 6; ++k) w[k] = sm[(t - 1) * 30 + 24 + k];
            bmv_full(A, w, se);
            #pragma unroll
            for (int k = 0; k < 6; ++k) se[k] += A[24 + k];
        }
        #pragma unroll
        for (int k = 0; k < 6; ++k)
            g_state[(size_t)k * (NCH * NB) + (2 * t) * NB + b] = se[k];
    }
}

// ---------------------------------------------------------------------------
// Pass 2 (PARALLEL): y[b][n] = ga . s0[0:4] + gb.xy . s0[4:6] + gb.z
// Block = 32x32 tile (tx = batch lane, ty = sample-in-tile). No recurrence.
// Output transposed through smem for coalesced [B][N] stores.
// ---------------------------------------------------------------------------
__global__ void __launch_bounds__(1024) out_kernel(float* __restrict__ out)
{
    __shared__ float buf[32 * 33];

    const int tx = threadIdx.x;     // batch lane
    const int ty = threadIdx.y;     // sample within tile
    const int n  = blockIdx.x * 32 + ty;
    const int c  = n / L_CHUNK;

    const int ofs = n * NB + tx;
    float4 ga = g_ga[ofs];
    float4 gb = g_gb[ofs];

    float y = gb.z;
    if (c > 0) {
        const size_t sb = (size_t)(c - 1) * NB + tx;
        y = fmaf(ga.x, g_state[0 * (size_t)(NCH * NB) + sb],
            fmaf(ga.y, g_state[1 * (size_t)(NCH * NB) + sb],
            fmaf(ga.z, g_state[2 * (size_t)(NCH * NB) + sb],
            fmaf(ga.w, g_state[3 * (size_t)(NCH * NB) + sb],
            fmaf(gb.x, g_state[4 * (size_t)(NCH * NB) + sb],
            fmaf(gb.y, g_state[5 * (size_t)(NCH * NB) + sb], gb.z))))));
    }

    buf[tx * 33 + ty] = y;
    __syncthreads();

    // transposed write: thread (tx,ty) writes row ty, sample base+tx
    out[(size_t)ty * NS + blockIdx.x * 32 + tx] = buf[ty * 33 + tx];
}

extern "C" void kernel_launch(void* const* d_in, const int* in_sizes, int n_in,
                              void* d_out, int out_size)
{
    const float* x       = (const float*)d_in[0];
    const float* alpha   = (const float*)d_in[1];
    const float* beta    = (const float*)d_in[2];
    const float* low_db  = (const float*)d_in[3];
    const float* mid_db  = (const float*)d_in[4];
    const float* mid_fc  = (const float*)d_in[5];
    const float* mid_Q   = (const float*)d_in[6];
    const float* high_db = (const float*)d_in[7];
    const float* alpha_a = (const float*)d_in[8];
    float* out = (float*)d_out;

    dim3 pb(16, 32);
    prep_kernel<<<NS / 16, pb>>>(x, alpha, beta, low_db, mid_db, mid_fc,
                                 mid_Q, high_db, alpha_a);
    map_kernel<<<NCH, 32>>>();
    scan_kernel<<<NB, 384>>>();
    dim3 ob(32, 32);
    out_kernel<<<NS / 32, ob>>>(out);
}

// round 16
// speedup vs baseline: 1.3550x; 1.0212x over previous
#include <cuda_runtime.h>
#include <math.h>

#define NB 32
#define NS 48000
#define L_CHUNK 64
#define NCH (NS / L_CHUNK)      /* 750 */
#define NPAIR (NCH / 2)         /* 375 */
#define PD1 4                   /* map prefetch depth */
#define PLANE (NS * NB)

// 3 planes of float4, layout [n][b]:
//   plane0 = (sA_low, invL, sA_high, invH)
//   plane1 = (cw_mid, alA, alrA, invM)
//   plane2 = (sv, alpha_a*y_attack, 1-alpha_a, 0)
__device__ float4 g_p0[(size_t)PLANE];
__device__ float4 g_p1[(size_t)PLANE];
__device__ float4 g_p2[(size_t)PLANE];
// Per-sample mix-folded output row: y = ga.s0123 + gb.s45 + gb.z
__device__ float4 g_ga[(size_t)PLANE];
__device__ float4 g_gb[(size_t)PLANE];
// Per (chunk, lane) affine map: 30 floats, [c][b][30]
__device__ float g_maps[(size_t)NCH * NB * 30];
// Inclusive chunk-end states: 6 planes of [c][b]
__device__ float g_state[6 * (size_t)NCH * NB];

// shelf constants
#define CW_L  0.9994645875f     /* cos(2pi*250/48000) */
#define ALC_L 0.0231360485f     /* sin(w0_l)*sqrt(2)/2 */
#define CW_H  0.8660254038f     /* cos(pi/6) */
#define ALC_H 0.3535533906f     /* sin(pi/6)*sqrt(2)/2 */
#define KDB   0.0830482024f     /* log2(10)/40 */

// ---------------- fast approx helpers ----------------
__device__ __forceinline__ float f_tanh(float x) {
    float r; asm("tanh.approx.f32 %0, %1;" : "=f"(r) : "f"(x)); return r;
}
__device__ __forceinline__ float f_rcp(float x) {
    float r; asm("rcp.approx.f32 %0, %1;" : "=f"(r) : "f"(x)); return r;
}
__device__ __forceinline__ float f_ex2(float x) {
    float r; asm("ex2.approx.f32 %0, %1;" : "=f"(r) : "f"(x)); return r;
}

// ---------------------------------------------------------------------------
// Coefficient reconstruction: pure FMA/MUL (reciprocals precomputed).
// ---------------------------------------------------------------------------
__device__ __forceinline__ void make_coefs(const float4& pa, const float4& pb, float c[15])
{
    {   // low shelf: pa.x = sA, pa.y = 1/a0
        float sA = pa.x, inv = pa.y;
        float A  = sA * sA;
        float t  = 2.0f * sA * ALC_L;
        float ap = A + 1.0f, am = A - 1.0f;
        c[0] = A * (ap - am * CW_L + t) * inv;
        c[1] = 2.0f * A * (am - ap * CW_L) * inv;
        c[2] = A * (ap - am * CW_L - t) * inv;
        c[3] = -2.0f * (am + ap * CW_L) * inv;
        c[4] = (ap + am * CW_L - t) * inv;
    }
    {   // mid peaking: pb = (cw, alA, alrA, 1/a0)
        float cw = pb.x, alA = pb.y, alrA = pb.z, inv = pb.w;
        c[5] = (1.0f + alA) * inv;
        c[6] = -2.0f * cw * inv;
        c[7] = (1.0f - alA) * inv;
        c[8] = c[6];
        c[9] = (1.0f - alrA) * inv;
    }
    {   // high shelf: pa.z = sA, pa.w = 1/a0
        float sA = pa.z, inv = pa.w;
        float A  = sA * sA;
        float t  = 2.0f * sA * ALC_H;
        float ap = A + 1.0f, am = A - 1.0f;
        c[10] = A * (ap + am * CW_H + t) * inv;
        c[11] = -2.0f * A * (am + ap * CW_H) * inv;
        c[12] = A * (ap + am * CW_H - t) * inv;
        c[13] = 2.0f * (am - ap * CW_H) * inv;
        c[14] = (ap - am * CW_H - t) * inv;
    }
}

// ---------------------------------------------------------------------------
// Kernel 1: transient sep, waveshaper, derived-param precompute.
// ---------------------------------------------------------------------------
__global__ void __launch_bounds__(512) prep_kernel(
        const float* __restrict__ x,
        const float* __restrict__ alpha,
        const float* __restrict__ beta,
        const float* __restrict__ low_db,
        const float* __restrict__ mid_db,
        const float* __restrict__ mid_fc,
        const float* __restrict__ mid_Q,
        const float* __restrict__ high_db,
        const float* __restrict__ alpha_a)
{
    __shared__ float4 st4[3 * 16 * 33];

    const int tx = threadIdx.x;
    const int ty = threadIdx.y;
    const int nbase = blockIdx.x * 16;
    const int n = nbase + tx;
    const int b = ty;
    const int i = b * NS + n;

    const float* xr = x + (size_t)b * NS;
    float xv = xr[n];
    float env = 0.0f;
    #pragma unroll
    for (int d = -7; d <= 7; ++d) {
        int j = n + d;
        if (j >= 0 && j < NS) env += fabsf(xr[j]);
    }
    env *= (1.0f / 15.0f);
    float xa = fabsf(xv);
    float gate = fmaf(0.5f, f_tanh(4.0f * (xa - env)), 0.5f);
    float av = gate * xv;
    float sv = (1.0f - gate) * xv;

    float be_ = beta[i];
    float ya = f_tanh(fmaf(alpha[i], av, be_)) - f_tanh(be_);

    float sA_l = f_ex2(low_db[i] * (0.5f * KDB));
    float sA_h = f_ex2(high_db[i] * (0.5f * KDB));

    float invL, invH;
    {
        float A = sA_l * sA_l, t = 2.0f * sA_l * ALC_L;
        invL = f_rcp((A + 1.0f) + (A - 1.0f) * CW_L + t);
    }
    {
        float A = sA_h * sA_h, t = 2.0f * sA_h * ALC_H;
        invH = f_rcp((A + 1.0f) - (A - 1.0f) * CW_H + t);
    }

    float A_m = f_ex2(mid_db[i] * KDB);
    float w0  = mid_fc[i] * 1.30899693e-4f;   // 2*pi/48000
    float sw = __sinf(w0), cw = __cosf(w0);
    float alq  = sw * 0.5f * f_rcp(mid_Q[i]);
    float alA  = alq * A_m;
    float alrA = alq * f_rcp(A_m);
    float invM = f_rcp(1.0f + alrA);

    float aav = alpha_a[i];

    st4[0 * (16 * 33) + tx * 33 + b] = make_float4(sA_l, invL, sA_h, invH);
    st4[1 * (16 * 33) + tx * 33 + b] = make_float4(cw, alA, alrA, invM);
    st4[2 * (16 * 33) + tx * 33 + b] = make_float4(sv, aav * ya, 1.0f - aav, 0.0f);

    __syncthreads();
    {
        const int tid = ty * 16 + tx;
        const int cb  = tid & 31;
        const int ctx = tid >> 5;
        const size_t o = (size_t)(nbase + ctx) * NB + cb;
        g_p0[o] = st4[0 * (16 * 33) + ctx * 33 + cb];
        g_p1[o] = st4[1 * (16 * 33) + ctx * 33 + cb];
        g_p2[o] = st4[2 * (16 * 33) + ctx * 33 + cb];
    }
}

// ---------------------------------------------------------------------------
// Step primitives on coefficient array c[15]. Each returns the tone-stack
// OUTPUT (y3) produced by this step — the output-row component.
// ---------------------------------------------------------------------------
__device__ __forceinline__ float stepF(const float c[15], float u[6], float v)
{
    float y1 = fmaf(c[0], v, u[0]);
    float a  = fmaf(c[1], v, fmaf(-c[3], y1, u[1]));
    float bb = fmaf(c[2], v, -c[4] * y1);
    float y2 = fmaf(c[5], y1, u[2]);
    float cc = fmaf(c[6], y1, fmaf(-c[8], y2, u[3]));
    float dd = fmaf(c[7], y1, -c[9] * y2);
    float y3 = fmaf(c[10], y2, u[4]);
    float ee = fmaf(c[11], y2, fmaf(-c[13], y3, u[5]));
    float ff = fmaf(c[12], y2, -c[14] * y3);
    u[0]=a; u[1]=bb; u[2]=cc; u[3]=dd; u[4]=ee; u[5]=ff;
    return y3;
}
__device__ __forceinline__ float stepM(const float c[15], float w[4])
{
    float y2 = w[0];
    float a  = fmaf(-c[8], y2, w[1]);
    float bb = -c[9] * y2;
    float y3 = fmaf(c[10], y2, w[2]);
    float cc = fmaf(c[11], y2, fmaf(-c[13], y3, w[3]));
    float dd = fmaf(c[12], y2, -c[14] * y3);
    w[0]=a; w[1]=bb; w[2]=cc; w[3]=dd;
    return y3;
}
__device__ __forceinline__ float stepH(const float c[15], float w[2])
{
    float y3 = w[0];
    float a  = fmaf(-c[13], y3, w[1]);
    float bb = -c[14] * y3;
    w[0]=a; w[1]=bb;
    return y3;
}

// ---------------------------------------------------------------------------
// Pass 1: per-chunk affine map + per-sample mix-folded OUTPUT ROW.
// One warp per 64-sample chunk. The 7 column pushes' y3 returns are exactly
// (G_n[0..5], H_n): y_n = G_n . s0 + H_n. Output-row components are dumped
// to smem IMMEDIATELY (STS.32, no live-range extension) and bulk-copied to
// g_ga/g_gb per 32-sample half, off the serial chain.
// ---------------------------------------------------------------------------
__global__ void __launch_bounds__(32) map_kernel()
{
    __shared__ float sg[7][32 * 33];   // 7 components x 32 samples, stride 33

    const int c = blockIdx.x;
    const int lane = threadIdx.x;
    const int n0 = c * L_CHUNK;

    const float4* __restrict__ p0 = g_p0;
    const float4* __restrict__ p1 = g_p1;
    const float4* __restrict__ p2 = g_p2;

    float u1[6] = {1,0,0,0,0,0};
    float u2[6] = {0,1,0,0,0,0};
    float u3[4] = {1,0,0,0};
    float u4[4] = {0,1,0,0};
    float u5[2] = {1,0};
    float u6[2] = {0,1};
    float dd[6] = {0,0,0,0,0,0};

    float4 qa[PD1], qb[PD1], qc[PD1];
    #pragma unroll
    for (int d = 0; d < PD1; ++d) {
        int ofs = (n0 + d) * NB + lane;
        qa[d] = p0[ofs]; qb[d] = p1[ofs]; qc[d] = p2[ofs];
    }

    for (int t = 0; t < L_CHUNK / 32; ++t) {
        const int nb_ = n0 + (t << 5);
        #pragma unroll
        for (int j = 0; j < 32; ++j) {
            const int slot = j & (PD1 - 1);
            float4 a = qa[slot], b = qb[slot], cc2 = qc[slot];
            int nf = nb_ + j + PD1;
            if (nf > NS - 1) nf = NS - 1;
            int ofs = nf * NB + lane;
            qa[slot] = p0[ofs]; qb[slot] = p1[ofs]; qc[slot] = p2[ofs];

            float cf[15];
            make_coefs(a, b, cf);

            const int so = j * 33 + lane;
            float z = cc2.z;                   // 1 - alpha_a
            sg[0][so] = z * stepF(cf, u1, 0.0f);
            sg[1][so] = z * stepF(cf, u2, 0.0f);
            sg[2][so] = z * stepM(cf, u3);
            sg[3][so] = z * stepM(cf, u4);
            sg[4][so] = z * stepH(cf, u5);
            sg[5][so] = z * stepH(cf, u6);
            sg[6][so] = fmaf(z, stepF(cf, dd, cc2.x), cc2.y);
        }
        __syncwarp();

        // bulk coalesced copy-out (independent, latency-tolerant)
        #pragma unroll 4
        for (int j = 0; j < 32; ++j) {
            const int so = j * 33 + lane;
            const int oc = (nb_ + j) * NB + lane;
            g_ga[oc] = make_float4(sg[0][so], sg[1][so], sg[2][so], sg[3][so]);
            g_gb[oc] = make_float4(sg[4][so], sg[5][so], sg[6][so], 0.0f);
        }
        __syncwarp();
    }

    float* rec = g_maps + (size_t)(c * NB + lane) * 30;
    #pragma unroll
    for (int k = 0; k < 6; ++k) rec[k]      = u1[k];
    #pragma unroll
    for (int k = 0; k < 6; ++k) rec[6 + k]  = u2[k];
    #pragma unroll
    for (int k = 0; k < 4; ++k) rec[12 + k] = u3[k];
    #pragma unroll
    for (int k = 0; k < 4; ++k) rec[16 + k] = u4[k];
    rec[20] = u5[0]; rec[21] = u5[1];
    rec[22] = u6[0]; rec[23] = u6[1];
    #pragma unroll
    for (int k = 0; k < 6; ++k) rec[24 + k] = dd[k];
}

// ---------------------------------------------------------------------------
// Map compose helpers (block-lower-triangular sparsity).
// ---------------------------------------------------------------------------
__device__ __forceinline__ void bmv_full(const float* B, const float* w, float* r)
{
    r[0] = w[0]*B[0] + w[1]*B[6];
    r[1] = w[0]*B[1] + w[1]*B[7];
    r[2] = w[0]*B[2] + w[1]*B[8]  + w[2]*B[12] + w[3]*B[16];
    r[3] = w[0]*B[3] + w[1]*B[9]  + w[2]*B[13] + w[3]*B[17];
    r[4] = w[0]*B[4] + w[1]*B[10] + w[2]*B[14] + w[3]*B[18] + w[4]*B[20] + w[5]*B[22];
    r[5] = w[0]*B[5] + w[1]*B[11] + w[2]*B[15] + w[3]*B[19] + w[4]*B[21] + w[5]*B[23];
}
__device__ __forceinline__ void bmv_mid(const float* B, const float* w, float* r)
{
    r[0] = w[0]*B[12] + w[1]*B[16];
    r[1] = w[0]*B[13] + w[1]*B[17];
    r[2] = w[0]*B[14] + w[1]*B[18] + w[2]*B[20] + w[3]*B[22];
    r[3] = w[0]*B[15] + w[1]*B[19] + w[2]*B[21] + w[3]*B[23];
}
__device__ __forceinline__ void bmv_high(const float* B, const float* w, float* r)
{
    r[0] = w[0]*B[20] + w[1]*B[22];
    r[1] = w[0]*B[21] + w[1]*B[23];
}
// C = B after A  (A applied first)
__device__ __forceinline__ void compose(const float* A, const float* B, float* C)
{
    bmv_full(B, A + 0,  C + 0);
    bmv_full(B, A + 6,  C + 6);
    bmv_mid (B, A + 12, C + 12);
    bmv_mid (B, A + 16, C + 16);
    bmv_high(B, A + 20, C + 20);
    bmv_high(B, A + 22, C + 22);
    float t6[6];
    bmv_full(B, A + 24, t6);
    #pragma unroll
    for (int k = 0; k < 6; ++k) C[24 + k] = t6[k] + B[24 + k];
}

// ---------------------------------------------------------------------------
// Scan: one block per batch lane. Pair-compose in registers, Hillis-Steele
// over 375 pairs in smem, emit both chunk-end states.
// ---------------------------------------------------------------------------
__global__ void __launch_bounds__(384) scan_kernel()
{
    __shared__ float sm[NPAIR * 30];    // 45000 B
    const int t = threadIdx.x;
    const int b = blockIdx.x;
    const bool on = (t < NPAIR);

    float A[30];
    if (on) {
        const float* srcA = g_maps + (size_t)((2 * t)     * NB + b) * 30;
        const float* srcB = g_maps + (size_t)((2 * t + 1) * NB + b) * 30;
        float Bm[30], P[30];
        #pragma unroll
        for (int k = 0; k < 30; ++k) A[k]  = srcA[k];
        #pragma unroll
        for (int k = 0; k < 30; ++k) Bm[k] = srcB[k];
        compose(A, Bm, P);
        #pragma unroll
        for (int k = 0; k < 30; ++k) sm[t * 30 + k] = P[k];
    }
    __syncthreads();

    for (int off = 1; off < NPAIR; off <<= 1) {
        float Ap[30], Bp[30];
        const bool act = on && (t >= off);
        if (act) {
            #pragma unroll
            for (int k = 0; k < 30; ++k) Ap[k] = sm[(t - off) * 30 + k];
            #pragma unroll
            for (int k = 0; k < 30; ++k) Bp[k] = sm[t * 30 + k];
        }
        __syncthreads();
        if (act) {
            float C[30];
            compose(Ap, Bp, C);
            #pragma unroll
            for (int k = 0; k < 30; ++k) sm[t * 30 + k] = C[k];
        }
        __syncthreads();
    }

    if (on) {
        #pragma unroll
        for (int k = 0; k < 6; ++k)
            g_state[(size_t)k * (NCH * NB) + (2 * t + 1) * NB + b] = sm[t * 30 + 24 + k];
        float se[6];
        if (t == 0) {
            #pragma unroll
            for (int k = 0; k < 6; ++k) se[k] = A[24 + k];
        } else {
            float w[6];
            #pragma unroll
            for (int k = 0; k < 6; ++k) w[k] = sm[(t - 1) * 30 + 24 + k];
            bmv_full(A, w, se);
            #pragma unroll
            for (int k = 0; k < 6; ++k) se[k] += A[24 + k];
        }
        #pragma unroll
        for (int k = 0; k < 6; ++k)
            g_state[(size_t)k * (NCH * NB) + (2 * t) * NB + b] = se[k];
    }
}

// ---------------------------------------------------------------------------
// Pass 2 (PARALLEL): y[b][n] = ga . s0[0:4] + gb.xy . s0[4:6] + gb.z
// Block = 32x32 tile (tx = batch lane, ty = sample-in-tile). No recurrence.
// Output transposed through smem for coalesced [B][N] stores.
// ---------------------------------------------------------------------------
__global__ void __launch_bounds__(1024) out_kernel(float* __restrict__ out)
{
    __shared__ float buf[32 * 33];

    const int tx = threadIdx.x;     // batch lane
    const int ty = threadIdx.y;     // sample within tile
    const int n  = blockIdx.x * 32 + ty;
    const int c  = n / L_CHUNK;

    const int ofs = n * NB + tx;
    float4 ga = g_ga[ofs];
    float4 gb = g_gb[ofs];

    float y = gb.z;
    if (c > 0) {
        const size_t sb = (size_t)(c - 1) * NB + tx;
        y = fmaf(ga.x, g_state[0 * (size_t)(NCH * NB) + sb],
            fmaf(ga.y, g_state[1 * (size_t)(NCH * NB) + sb],
            fmaf(ga.z, g_state[2 * (size_t)(NCH * NB) + sb],
            fmaf(ga.w, g_state[3 * (size_t)(NCH * NB) + sb],
            fmaf(gb.x, g_state[4 * (size_t)(NCH * NB) + sb],
            fmaf(gb.y, g_state[5 * (size_t)(NCH * NB) + sb], gb.z))))));
    }

    buf[tx * 33 + ty] = y;
    __syncthreads();

    // transposed write: thread (tx,ty) writes row ty, sample base+tx
    out[(size_t)ty * NS + blockIdx.x * 32 + tx] = buf[ty * 33 + tx];
}

extern "C" void kernel_launch(void* const* d_in, const int* in_sizes, int n_in,
                              void* d_out, int out_size)
{
    const float* x       = (const float*)d_in[0];
    const float* alpha   = (const float*)d_in[1];
    const float* beta    = (const float*)d_in[2];
    const float* low_db  = (const float*)d_in[3];
    const float* mid_db  = (const float*)d_in[4];
    const float* mid_fc  = (const float*)d_in[5];
    const float* mid_Q   = (const float*)d_in[6];
    const float* high_db = (const float*)d_in[7];
    const float* alpha_a = (const float*)d_in[8];
    float* out = (float*)d_out;

    dim3 pb(16, 32);
    prep_kernel<<<NS / 16, pb>>>(x, alpha, beta, low_db, mid_db, mid_fc,
                                 mid_Q, high_db, alpha_a);
    map_kernel<<<NCH, 32>>>();
    scan_kernel<<<NB, 384>>>();
    dim3 ob(32, 32);
    out_kernel<<<NS / 32, ob>>>(out);
}